// round 2
// baseline (speedup 1.0000x reference)
#include <cuda_runtime.h>
#include <cuda_bf16.h>
#include <math.h>

// Problem constants
#define B_  2
#define N_  2048
#define D_  1024
#define H_  16
#define DP_ 64
#define EQ_ (3 * H_ * DP_)   // 3072
#define M_ROWS (B_ * N_)     // 4096

// Scratch (no cudaMalloc allowed)
__device__ float g_qkv[(size_t)M_ROWS * EQ_];    // 48 MB
__device__ float g_attn[(size_t)M_ROWS * D_];    // 16 MB

// ---------------------------------------------------------------------------
// Tiled SGEMM with bias: C[M,N] = A[M,K] @ B[K,N] + bias[N]
// BM=BN=128, BK=16, 256 threads, 8x8 per-thread tile
// ---------------------------------------------------------------------------
#define BM 128
#define BN 128
#define BK 16
#define TM 8
#define TN 8

__global__ __launch_bounds__(256) void sgemm_bias_kernel(
    const float* __restrict__ A, const float* __restrict__ Bm,
    const float* __restrict__ bias, float* __restrict__ C,
    int M, int N, int K)
{
    __shared__ float As[BK][BM];
    __shared__ float Bs[BK][BN];

    const int tid = threadIdx.x;
    const int block_row = blockIdx.y * BM;
    const int block_col = blockIdx.x * BN;

    const int tx = tid % (BN / TN);   // 0..15
    const int ty = tid / (BN / TN);   // 0..15

    // A-load mapping: 128 rows x 4 float4 per row = 512 float4; 2 per thread
    const int aRow  = tid >> 2;       // 0..63
    const int aCol4 = tid & 3;        // 0..3
    // B-load mapping: 16 rows x 32 float4 per row = 512 float4; 2 per thread
    const int bRow  = tid >> 5;       // 0..7
    const int bCol4 = tid & 31;       // 0..31

    float acc[TM][TN];
#pragma unroll
    for (int i = 0; i < TM; i++)
#pragma unroll
        for (int j = 0; j < TN; j++) acc[i][j] = 0.f;

    for (int k0 = 0; k0 < K; k0 += BK) {
#pragma unroll
        for (int p = 0; p < 2; p++) {
            int r = aRow + p * 64;
            float4 v = *(const float4*)&A[(size_t)(block_row + r) * K + k0 + aCol4 * 4];
            As[aCol4 * 4 + 0][r] = v.x;
            As[aCol4 * 4 + 1][r] = v.y;
            As[aCol4 * 4 + 2][r] = v.z;
            As[aCol4 * 4 + 3][r] = v.w;
        }
#pragma unroll
        for (int p = 0; p < 2; p++) {
            int r = bRow + p * 8;
            *(float4*)&Bs[r][bCol4 * 4] =
                *(const float4*)&Bm[(size_t)(k0 + r) * N + block_col + bCol4 * 4];
        }
        __syncthreads();

#pragma unroll
        for (int kk = 0; kk < BK; kk++) {
            float ra[TM], rb[TN];
#pragma unroll
            for (int i = 0; i < TM; i++) ra[i] = As[kk][ty * TM + i];
#pragma unroll
            for (int j = 0; j < TN; j++) rb[j] = Bs[kk][tx * TN + j];
#pragma unroll
            for (int i = 0; i < TM; i++)
#pragma unroll
                for (int j = 0; j < TN; j++)
                    acc[i][j] += ra[i] * rb[j];
        }
        __syncthreads();
    }

#pragma unroll
    for (int i = 0; i < TM; i++) {
        int row = block_row + ty * TM + i;
#pragma unroll
        for (int j = 0; j < TN; j += 4) {
            int col = block_col + tx * TN + j;
            float4 v;
            v.x = acc[i][j + 0] + bias[col + 0];
            v.y = acc[i][j + 1] + bias[col + 1];
            v.z = acc[i][j + 2] + bias[col + 2];
            v.w = acc[i][j + 3] + bias[col + 3];
            *(float4*)&C[(size_t)row * N + col] = v;
        }
    }
}

// ---------------------------------------------------------------------------
// Flash-attention: one CTA per (b, h, 64-query tile). 256 threads.
// qkv layout: [B*N, 3072] where col = h*192 + (q:0-63 | k:64-127 | v:128-191)
// out layout: [B*N, 1024] where col = h*64 + d
// ---------------------------------------------------------------------------
#define TLD 68   // padded row stride (floats) for 64-wide tiles

__global__ __launch_bounds__(256) void attn_kernel(
    const float* __restrict__ qkv, float* __restrict__ out)
{
    extern __shared__ float sm[];
    float* Qs  = sm;                  // 64 * 68
    float* Ks  = Qs + 64 * TLD;
    float* Vs  = Ks + 64 * TLD;
    float* Ss  = Vs + 64 * TLD;
    float* m_s = Ss + 64 * TLD;       // 64
    float* l_s = m_s + 64;            // 64
    float* f_s = l_s + 64;            // 64

    const int tid = threadIdx.x;
    const int qt = blockIdx.x;        // query tile (0..31)
    const int h  = blockIdx.y;        // head
    const int b  = blockIdx.z;        // batch

    const int tx = tid & 15;          // 0..15
    const int ty = tid >> 4;          // 0..15
    const int srow = ty * 4;
    const int scol = tx * 4;

    const int q0 = qt * 64;
    const int hq = h * 192;

    // Load Q tile (scaled by 1/sqrt(DP) = 0.125)
#pragma unroll
    for (int p = 0; p < 4; p++) {
        int idx = tid + p * 256;         // 0..1023
        int r = idx >> 4;
        int c = (idx & 15) * 4;
        float4 v = *(const float4*)&qkv[(size_t)(b * N_ + q0 + r) * EQ_ + hq + c];
        v.x *= 0.125f; v.y *= 0.125f; v.z *= 0.125f; v.w *= 0.125f;
        *(float4*)&Qs[r * TLD + c] = v;
    }
    if (tid < 64) { m_s[tid] = -3.0e38f; l_s[tid] = 0.f; }

    float acc[4][4];
#pragma unroll
    for (int i = 0; i < 4; i++)
#pragma unroll
        for (int j = 0; j < 4; j++) acc[i][j] = 0.f;

    for (int kt = 0; kt < N_ / 64; kt++) {
        __syncthreads();   // protect Ks/Vs/Ss reuse (and Qs/m/l init on iter 0)
        const int k0 = kt * 64;
#pragma unroll
        for (int p = 0; p < 4; p++) {
            int idx = tid + p * 256;
            int r = idx >> 4;
            int c = (idx & 15) * 4;
            size_t g = (size_t)(b * N_ + k0 + r) * EQ_ + hq;
            *(float4*)&Ks[r * TLD + c] = *(const float4*)&qkv[g + 64 + c];
            *(float4*)&Vs[r * TLD + c] = *(const float4*)&qkv[g + 128 + c];
        }
        __syncthreads();

        // S = Q @ K^T  (4x4 per thread)
        float s[4][4];
#pragma unroll
        for (int i = 0; i < 4; i++)
#pragma unroll
            for (int j = 0; j < 4; j++) s[i][j] = 0.f;

        for (int d = 0; d < 64; d += 4) {
            float4 qa[4], kb[4];
#pragma unroll
            for (int i = 0; i < 4; i++) qa[i] = *(float4*)&Qs[(srow + i) * TLD + d];
#pragma unroll
            for (int j = 0; j < 4; j++) kb[j] = *(float4*)&Ks[(scol + j) * TLD + d];
#pragma unroll
            for (int i = 0; i < 4; i++)
#pragma unroll
                for (int j = 0; j < 4; j++) {
                    s[i][j] += qa[i].x * kb[j].x + qa[i].y * kb[j].y
                             + qa[i].z * kb[j].z + qa[i].w * kb[j].w;
                }
        }
#pragma unroll
        for (int i = 0; i < 4; i++)
#pragma unroll
            for (int j = 0; j < 4; j++)
                Ss[(srow + i) * TLD + scol + j] = s[i][j];
        __syncthreads();

        // Online softmax: row = tid/4, 4 threads per row (16 cols each)
        {
            const int row = tid >> 2;
            const int qq  = tid & 3;
            float* srcp = &Ss[row * TLD + qq * 16];
            float tm = -3.0e38f;
#pragma unroll
            for (int c = 0; c < 16; c++) tm = fmaxf(tm, srcp[c]);
            tm = fmaxf(tm, __shfl_xor_sync(0xffffffffu, tm, 1));
            tm = fmaxf(tm, __shfl_xor_sync(0xffffffffu, tm, 2));
            float mold = m_s[row];
            float mnew = fmaxf(mold, tm);
            float rs = 0.f;
#pragma unroll
            for (int c = 0; c < 16; c++) {
                float e = __expf(srcp[c] - mnew);
                srcp[c] = e;
                rs += e;
            }
            rs += __shfl_xor_sync(0xffffffffu, rs, 1);
            rs += __shfl_xor_sync(0xffffffffu, rs, 2);
            if (qq == 0) {
                float f = __expf(mold - mnew);
                m_s[row] = mnew;
                l_s[row] = l_s[row] * f + rs;
                f_s[row] = f;
            }
        }
        __syncthreads();

        // Rescale accumulators, then acc += P @ V
#pragma unroll
        for (int i = 0; i < 4; i++) {
            float f = f_s[srow + i];
#pragma unroll
            for (int j = 0; j < 4; j++) acc[i][j] *= f;
        }
        for (int k = 0; k < 64; k++) {
            float p[4], vv[4];
#pragma unroll
            for (int i = 0; i < 4; i++) p[i] = Ss[(srow + i) * TLD + k];
#pragma unroll
            for (int j = 0; j < 4; j++) vv[j] = Vs[k * TLD + scol + j];
#pragma unroll
            for (int i = 0; i < 4; i++)
#pragma unroll
                for (int j = 0; j < 4; j++) acc[i][j] += p[i] * vv[j];
        }
    }
    __syncthreads();

#pragma unroll
    for (int i = 0; i < 4; i++) {
        float inv = 1.0f / l_s[srow + i];
        int q = q0 + srow + i;
#pragma unroll
        for (int j = 0; j < 4; j++) {
            out[(size_t)(b * N_ + q) * D_ + h * DP_ + scol + j] = acc[i][j] * inv;
        }
    }
}

// ---------------------------------------------------------------------------
// Launch
// ---------------------------------------------------------------------------
extern "C" void kernel_launch(void* const* d_in, const int* in_sizes, int n_in,
                              void* d_out, int out_size)
{
    const float* x     = (const float*)d_in[0];
    const float* W_qkv = (const float*)d_in[1];
    const float* b_qkv = (const float*)d_in[2];
    const float* W_out = (const float*)d_in[3];
    const float* b_out = (const float*)d_in[4];
    float* out = (float*)d_out;

    float* qkv;  cudaGetSymbolAddress((void**)&qkv, g_qkv);
    float* attn; cudaGetSymbolAddress((void**)&attn, g_attn);

    // 1) QKV projection: [4096,1024] @ [1024,3072] + b
    {
        dim3 grid(EQ_ / BN, M_ROWS / BM);   // (24, 32)
        sgemm_bias_kernel<<<grid, 256>>>(x, W_qkv, b_qkv, qkv, M_ROWS, EQ_, D_);
    }

    // 2) Attention
    {
        const int smem = (4 * 64 * TLD + 3 * 64) * (int)sizeof(float);  // 70400 B
        cudaFuncSetAttribute(attn_kernel, cudaFuncAttributeMaxDynamicSharedMemorySize, smem);
        dim3 grid(N_ / 64, H_, B_);         // (32, 16, 2)
        attn_kernel<<<grid, 256, smem>>>(qkv, attn);
    }

    // 3) Output projection: [4096,1024] @ [1024,1024] + b
    {
        dim3 grid(D_ / BN, M_ROWS / BM);    // (8, 32)
        sgemm_bias_kernel<<<grid, 256>>>(attn, W_out, b_out, out, M_ROWS, D_, D_);
    }
}

// round 4
// speedup vs baseline: 4.0170x; 4.0170x over previous
#include <cuda_runtime.h>
#include <cstdint>
#include <cstddef>

// Problem constants
#define B_  2
#define N_  2048
#define D_  1024
#define H_  16
#define DP_ 64
#define EQ_ 3072            // 3*H*DP
#define M_ROWS 4096         // B*N

// Scratch (no allocations allowed)
__device__ float g_qkv [(size_t)M_ROWS * EQ_];   // 48 MB
__device__ float g_attn[(size_t)M_ROWS * D_];    // 16 MB

// ---------------------------------------------------------------------------
// Helpers
// ---------------------------------------------------------------------------
__device__ __forceinline__ uint32_t smem_u32(const void* p) {
    uint32_t a;
    asm("{ .reg .u64 t; cvta.to.shared.u64 t, %1; cvt.u32.u64 %0, t; }"
        : "=r"(a) : "l"(p));
    return a;
}

__device__ __forceinline__ uint32_t f2tf(float x) {
    uint32_t r;
    asm("cvt.rna.tf32.f32 %0, %1;" : "=r"(r) : "f"(x));
    return r;
}

__device__ __forceinline__ void cp16(uint32_t dst, const float* src) {
    asm volatile("cp.async.cg.shared.global [%0], [%1], 16;"
                 :: "r"(dst), "l"(__cvta_generic_to_global(src)));
}
#define CP_COMMIT asm volatile("cp.async.commit_group;" ::: "memory")
#define CP_WAIT0  asm volatile("cp.async.wait_group 0;" ::: "memory")
#define CP_WAIT1  asm volatile("cp.async.wait_group 1;" ::: "memory")

// D += A(16x8 tf32, row) * B(8x8 tf32, col)
__device__ __forceinline__ void mma8(float d[4], const uint32_t a[4], const uint32_t b[2]) {
    asm volatile(
        "mma.sync.aligned.m16n8k8.row.col.f32.tf32.tf32.f32 "
        "{%0,%1,%2,%3}, {%4,%5,%6,%7}, {%8,%9}, {%0,%1,%2,%3};"
        : "+f"(d[0]), "+f"(d[1]), "+f"(d[2]), "+f"(d[3])
        : "r"(a[0]), "r"(a[1]), "r"(a[2]), "r"(a[3]), "r"(b[0]), "r"(b[1]));
}

// ---------------------------------------------------------------------------
// GEMM: C[M,Nn] = A[M,K] @ B[K,Nn] + bias  (all row-major, tf32 mma.sync)
// CTA 128x128, KC=32, 8 warps (2x4) of 64x32, cp.async double buffered.
// smem: A [2][128][36] (18432B/stage), B [2][32][136] (17408B/stage)
// ---------------------------------------------------------------------------
#define GEMM_SMEM (2*18432 + 2*17408)

__global__ __launch_bounds__(256) void gemm_tc(
    const float* __restrict__ A, const float* __restrict__ Bw,
    const float* __restrict__ bias, float* __restrict__ C,
    int M, int Nn, int K)
{
    extern __shared__ char smem[];
    const uint32_t sA0 = smem_u32(smem);
    const uint32_t sB0 = sA0 + 2*18432;
    float* fA = (float*)smem;
    float* fB = (float*)(smem + 2*18432);

    const int tid = threadIdx.x;
    const int wid = tid >> 5, lane = tid & 31;
    const int gid = lane >> 2, tig = lane & 3;
    const int wm = wid >> 2, wn = wid & 3;
    const int m0 = blockIdx.y * 128, n0 = blockIdx.x * 128;

    float acc[4][4][4];
#pragma unroll
    for (int i = 0; i < 4; i++)
#pragma unroll
        for (int j = 0; j < 4; j++)
#pragma unroll
            for (int r = 0; r < 4; r++) acc[i][j][r] = 0.f;

    // chunk loader
    auto load_chunk = [&](int k0, int s) {
        const uint32_t da = sA0 + s * 18432;
        const uint32_t db = sB0 + s * 17408;
#pragma unroll
        for (int p = 0; p < 4; p++) {
            int idx = tid + p * 256;
            int m = idx >> 3, k4 = (idx & 7) * 4;
            cp16(da + (m * 36 + k4) * 4, A + (size_t)(m0 + m) * K + k0 + k4);
        }
#pragma unroll
        for (int p = 0; p < 4; p++) {
            int idx = tid + p * 256;
            int kr = idx >> 5, n4 = (idx & 31) * 4;
            cp16(db + (kr * 136 + n4) * 4, Bw + (size_t)(k0 + kr) * Nn + n0 + n4);
        }
        CP_COMMIT;
    };

    load_chunk(0, 0);
    const int nch = K >> 5;
    for (int c = 0; c < nch; c++) {
        if (c + 1 < nch) { load_chunk((c + 1) * 32, (c + 1) & 1); CP_WAIT1; }
        else             { CP_WAIT0; }
        __syncthreads();

        const float* cA = fA + (c & 1) * 4608;
        const float* cB = fB + (c & 1) * 4352;

#pragma unroll
        for (int kk = 0; kk < 4; kk++) {
            const int k = kk * 8;
            uint32_t af[4][4], bf[4][2];
#pragma unroll
            for (int mt = 0; mt < 4; mt++) {
                const float* pr = cA + (wm * 64 + mt * 16 + gid) * 36 + k + tig;
                af[mt][0] = f2tf(pr[0]);
                af[mt][1] = f2tf(pr[8 * 36]);
                af[mt][2] = f2tf(pr[4]);
                af[mt][3] = f2tf(pr[8 * 36 + 4]);
            }
#pragma unroll
            for (int nt = 0; nt < 4; nt++) {
                const float* pc = cB + (k + tig) * 136 + wn * 32 + nt * 8 + gid;
                bf[nt][0] = f2tf(pc[0]);
                bf[nt][1] = f2tf(pc[4 * 136]);
            }
#pragma unroll
            for (int mt = 0; mt < 4; mt++)
#pragma unroll
                for (int nt = 0; nt < 4; nt++)
                    mma8(acc[mt][nt], af[mt], bf[nt]);
        }
        __syncthreads();
    }

    // epilogue
#pragma unroll
    for (int mt = 0; mt < 4; mt++) {
        const int row = m0 + wm * 64 + mt * 16 + gid;
#pragma unroll
        for (int nt = 0; nt < 4; nt++) {
            const int col = n0 + wn * 32 + nt * 8 + 2 * tig;
            float2 bv = *(const float2*)(bias + col);
            float2 o0, o1;
            o0.x = acc[mt][nt][0] + bv.x; o0.y = acc[mt][nt][1] + bv.y;
            o1.x = acc[mt][nt][2] + bv.x; o1.y = acc[mt][nt][3] + bv.y;
            *(float2*)(C + (size_t)row * Nn + col) = o0;
            *(float2*)(C + (size_t)(row + 8) * Nn + col) = o1;
        }
    }
}

// ---------------------------------------------------------------------------
// Flash attention (tf32 mma.sync): CTA = (b, h, 128-query tile), 8 warps,
// each warp owns 16 full query rows. K/V double-buffered cp.async.
// smem: QP [128][68] @0 | K [2][64][68] @34816 | V [2][64][72] @69632
// ---------------------------------------------------------------------------
#define FLASH_SMEM (34816 + 2*17408 + 2*18432)

__global__ __launch_bounds__(256) void flash_tc(
    const float* __restrict__ qkv, float* __restrict__ attn)
{
    extern __shared__ char smem[];
    float*    fQP = (float*)smem;
    uint32_t* uQP = (uint32_t*)smem;
    float*    fK  = (float*)(smem + 34816);
    float*    fV  = (float*)(smem + 69632);
    const uint32_t sQP = smem_u32(smem);
    const uint32_t sK  = sQP + 34816;
    const uint32_t sV  = sQP + 69632;

    const int tid = threadIdx.x, wid = tid >> 5, lane = tid & 31;
    const int gid = lane >> 2, tig = lane & 3;
    const int qt = blockIdx.x, h = blockIdx.y, b = blockIdx.z;
    const size_t rowbase = (size_t)(b * N_) * EQ_ + h * 192;
    const int q0 = qt * 128;

    auto load_kv = [&](int t, int s) {
#pragma unroll
        for (int p = 0; p < 4; p++) {
            int idx = tid + p * 256;
            int r = idx >> 4, c4 = (idx & 15) * 4;
            const float* g = qkv + rowbase + (size_t)(t * 64 + r) * EQ_;
            cp16(sK + s * 17408 + (r * 68 + c4) * 4, g + 64 + c4);
            cp16(sV + s * 18432 + (r * 72 + c4) * 4, g + 128 + c4);
        }
        CP_COMMIT;
    };

    // prologue: Q + first K/V in one commit group
#pragma unroll
    for (int p = 0; p < 8; p++) {
        int idx = tid + p * 256;
        int r = idx >> 4, c4 = (idx & 15) * 4;
        cp16(sQP + (r * 68 + c4) * 4, qkv + rowbase + (size_t)(q0 + r) * EQ_ + c4);
    }
    load_kv(0, 0);

    uint32_t qf[8][4];
    float o[8][4];
#pragma unroll
    for (int nt = 0; nt < 8; nt++)
#pragma unroll
        for (int r = 0; r < 4; r++) o[nt][r] = 0.f;
    float m0r = -1e30f, m1r = -1e30f, l0r = 0.f, l1r = 0.f;

    for (int t = 0; t < N_ / 64; t++) {
        if (t + 1 < N_ / 64) { load_kv(t + 1, (t + 1) & 1); CP_WAIT1; }
        else                 { CP_WAIT0; }
        __syncthreads();

        if (t == 0) {
            // build persistent Q fragments (scaled by 1/sqrt(DP)=0.125)
#pragma unroll
            for (int kk = 0; kk < 8; kk++) {
                const float* pr = fQP + (wid * 16 + gid) * 68 + kk * 8 + tig;
                qf[kk][0] = f2tf(pr[0] * 0.125f);
                qf[kk][1] = f2tf(pr[8 * 68] * 0.125f);
                qf[kk][2] = f2tf(pr[4] * 0.125f);
                qf[kk][3] = f2tf(pr[8 * 68 + 4] * 0.125f);
            }
        }
        const float* cK = fK + (t & 1) * 4352;
        const float* cV = fV + (t & 1) * 4608;

        // S = Q @ K^T (warp: 16 x 64)
        float sc[8][4];
#pragma unroll
        for (int nt = 0; nt < 8; nt++)
#pragma unroll
            for (int r = 0; r < 4; r++) sc[nt][r] = 0.f;
#pragma unroll
        for (int kk = 0; kk < 8; kk++) {
#pragma unroll
            for (int nt = 0; nt < 8; nt++) {
                uint32_t bf[2];
                const float* pc = cK + (nt * 8 + gid) * 68 + kk * 8 + tig;
                bf[0] = f2tf(pc[0]);
                bf[1] = f2tf(pc[4]);
                mma8(sc[nt], qf[kk], bf);
            }
        }

        // online softmax (rows gid, gid+8; reduce over 4-lane quad)
        float mx0 = sc[0][0], mx1 = sc[0][2];
#pragma unroll
        for (int nt = 0; nt < 8; nt++) {
            mx0 = fmaxf(mx0, fmaxf(sc[nt][0], sc[nt][1]));
            mx1 = fmaxf(mx1, fmaxf(sc[nt][2], sc[nt][3]));
        }
        mx0 = fmaxf(mx0, __shfl_xor_sync(0xffffffffu, mx0, 1));
        mx0 = fmaxf(mx0, __shfl_xor_sync(0xffffffffu, mx0, 2));
        mx1 = fmaxf(mx1, __shfl_xor_sync(0xffffffffu, mx1, 1));
        mx1 = fmaxf(mx1, __shfl_xor_sync(0xffffffffu, mx1, 2));

        const float mn0 = fmaxf(m0r, mx0), mn1 = fmaxf(m1r, mx1);
        const float scl0 = __expf(m0r - mn0), scl1 = __expf(m1r - mn1);
        m0r = mn0; m1r = mn1;

        float sum0 = 0.f, sum1 = 0.f;
#pragma unroll
        for (int nt = 0; nt < 8; nt++) {
            sc[nt][0] = __expf(sc[nt][0] - mn0); sum0 += sc[nt][0];
            sc[nt][1] = __expf(sc[nt][1] - mn0); sum0 += sc[nt][1];
            sc[nt][2] = __expf(sc[nt][2] - mn1); sum1 += sc[nt][2];
            sc[nt][3] = __expf(sc[nt][3] - mn1); sum1 += sc[nt][3];
        }
        l0r = l0r * scl0 + sum0;
        l1r = l1r * scl1 + sum1;
#pragma unroll
        for (int nt = 0; nt < 8; nt++) {
            o[nt][0] *= scl0; o[nt][1] *= scl0;
            o[nt][2] *= scl1; o[nt][3] *= scl1;
        }

        // write P (tf32) into QP region (warp-private rows)
        uint32_t* pb0 = uQP + (wid * 16 + gid) * 68 + 2 * tig;
        uint32_t* pb1 = uQP + (wid * 16 + gid + 8) * 68 + 2 * tig;
#pragma unroll
        for (int nt = 0; nt < 8; nt++) {
            uint2 u0; u0.x = f2tf(sc[nt][0]); u0.y = f2tf(sc[nt][1]);
            uint2 u1; u1.x = f2tf(sc[nt][2]); u1.y = f2tf(sc[nt][3]);
            *(uint2*)(pb0 + nt * 8) = u0;
            *(uint2*)(pb1 + nt * 8) = u1;
        }
        __syncwarp();

        // O += P @ V
#pragma unroll
        for (int kk = 0; kk < 8; kk++) {
            uint32_t af[4];
            const uint32_t* pp = uQP + (wid * 16 + gid) * 68 + kk * 8 + tig;
            af[0] = pp[0];
            af[1] = pp[8 * 68];
            af[2] = pp[4];
            af[3] = pp[8 * 68 + 4];
#pragma unroll
            for (int nt = 0; nt < 8; nt++) {
                uint32_t bf[2];
                const float* pv = cV + (kk * 8 + tig) * 72 + nt * 8 + gid;
                bf[0] = f2tf(pv[0]);
                bf[1] = f2tf(pv[4 * 72]);
                mma8(o[nt], af, bf);
            }
        }
        __syncthreads();
    }

    // finalize
    l0r += __shfl_xor_sync(0xffffffffu, l0r, 1);
    l0r += __shfl_xor_sync(0xffffffffu, l0r, 2);
    l1r += __shfl_xor_sync(0xffffffffu, l1r, 1);
    l1r += __shfl_xor_sync(0xffffffffu, l1r, 2);
    const float inv0 = 1.0f / l0r, inv1 = 1.0f / l1r;

    const int q = b * N_ + q0 + wid * 16 + gid;
    float* or0 = attn + (size_t)q * D_ + h * 64 + 2 * tig;
    float* or1 = attn + (size_t)(q + 8) * D_ + h * 64 + 2 * tig;
#pragma unroll
    for (int nt = 0; nt < 8; nt++) {
        float2 v0; v0.x = o[nt][0] * inv0; v0.y = o[nt][1] * inv0;
        float2 v1; v1.x = o[nt][2] * inv1; v1.y = o[nt][3] * inv1;
        *(float2*)(or0 + nt * 8) = v0;
        *(float2*)(or1 + nt * 8) = v1;
    }
}

// ---------------------------------------------------------------------------
// Launch
// ---------------------------------------------------------------------------
extern "C" void kernel_launch(void* const* d_in, const int* in_sizes, int n_in,
                              void* d_out, int out_size)
{
    const float* x     = (const float*)d_in[0];
    const float* W_qkv = (const float*)d_in[1];
    const float* b_qkv = (const float*)d_in[2];
    const float* W_out = (const float*)d_in[3];
    const float* b_out = (const float*)d_in[4];
    float* out = (float*)d_out;

    float *qkv, *attn;
    cudaGetSymbolAddress((void**)&qkv,  g_qkv);
    cudaGetSymbolAddress((void**)&attn, g_attn);

    cudaFuncSetAttribute(gemm_tc,  cudaFuncAttributeMaxDynamicSharedMemorySize, GEMM_SMEM);
    cudaFuncSetAttribute(flash_tc, cudaFuncAttributeMaxDynamicSharedMemorySize, FLASH_SMEM);

    // 1) QKV projection: [4096,3072] = x[4096,1024] @ W_qkv[1024,3072] + b_qkv
    gemm_tc<<<dim3(EQ_ / 128, M_ROWS / 128), 256, GEMM_SMEM>>>(
        x, W_qkv, b_qkv, qkv, M_ROWS, EQ_, D_);

    // 2) fused flash attention -> attn[4096,1024]
    flash_tc<<<dim3(N_ / 128, H_, B_), 256, FLASH_SMEM>>>(qkv, attn);

    // 3) output projection: out = attn @ W_out[1024,1024] + b_out
    gemm_tc<<<dim3(D_ / 128, M_ROWS / 128), 256, GEMM_SMEM>>>(
        attn, W_out, b_out, out, M_ROWS, D_, D_);
}